// round 9
// baseline (speedup 1.0000x reference)
#include <cuda_runtime.h>

// TokenEmbedding segment-sum, two-phase with Programmatic Dependent Launch:
//   Phase A: scatter packed bounds seg2[b][t] = (start[t], start[t+1]);
//            each block fences + triggers programmatic completion.
//   Phase B: launched with ProgrammaticStreamSerialization. Prologue
//            (self-covering L2 prefetch of row w==t) runs CONCURRENTLY with
//            phase A; cudaGridDependencySynchronize() gates only the bounds
//            load. Hot loop: 128 threads, 2 float4 columns each (champion).

#define B_DIM 8
#define L_DIM 4096
#define H_DIM 1024
#define H4   (H_DIM / 4)   // 256 float4 per row
#define TB   128           // phase-B threads; each owns 2 float4 columns

// packed bounds: seg2[b][t] = { start[t], start[t+1] }
__device__ int2 g_seg2[B_DIM][L_DIM];

__global__ __launch_bounds__(256) void seg_bounds_kernel(
    const int* __restrict__ w2t)      // [B, L] sorted per row
{
    const int b = blockIdx.y;
    const int w = blockIdx.x * blockDim.x + threadIdx.x;

    if (w < L_DIM) {
        const int* idx = w2t + (size_t)b * L_DIM;
        const int cur  = __ldg(idx + w);
        const int prev = (w > 0) ? __ldg(idx + w - 1) : -1;

        for (int t = prev + 1; t <= cur; ++t) {
            g_seg2[b][t].x = w;                  // lo of token t
            if (t >= 1) g_seg2[b][t - 1].y = w;  // hi of token t-1
        }
        if (w == L_DIM - 1) {
            for (int t = cur + 1; t <= L_DIM; ++t) {
                if (t < L_DIM) g_seg2[b][t].x = L_DIM;
                g_seg2[b][t - 1].y = L_DIM;
            }
        }
    }

    // make this block's writes visible, then allow the dependent grid to
    // pass its griddepcontrol.wait once every block has triggered
    __threadfence();
    __syncthreads();
    cudaTriggerProgrammaticLaunchCompletion();
}

__global__ __launch_bounds__(TB) void token_segsum_kernel(
    const float* __restrict__ x,      // [B, L, H]
    float*       __restrict__ out)    // [B, L, H]
{
    const int t = blockIdx.x;   // token id
    const int b = blockIdx.y;   // batch

    const float* __restrict__ xb = x + (size_t)b * L_DIM * H_DIM;

    // --- prologue: independent of phase A, overlaps it under PDL ---
    // self-covering L2 prefetch of row w==t (t<->w bijection over the grid):
    // row = 4096 B = 32 x 128B lines; threads 0..31 prefetch one line each.
    if (threadIdx.x < 32) {
        const float* p = xb + (size_t)t * H_DIM + threadIdx.x * 32;
        asm volatile("prefetch.global.L2 [%0];" :: "l"(p));
    }

    // --- wait for phase A's bounds to be visible ---
    cudaGridDependencySynchronize();

    const int2 bnd = __ldg(&g_seg2[b][t]);
    const int lo = bnd.x;
    const int hi = bnd.y;

    const int c = threadIdx.x;  // float4 column 0..127 (also owns c+128)
    const float4* __restrict__ rows = reinterpret_cast<const float4*>(xb);

    float4 a0 = make_float4(0.f, 0.f, 0.f, 0.f);
    float4 a1 = a0;

    for (int w = lo; w < hi; ++w) {
        const float4* r = rows + (size_t)w * H4;
        float4 v0 = __ldcs(r + c);
        float4 v1 = __ldcs(r + c + TB);
        a0.x += v0.x; a0.y += v0.y; a0.z += v0.z; a0.w += v0.w;
        a1.x += v1.x; a1.y += v1.y; a1.z += v1.z; a1.w += v1.w;
    }

    float4* __restrict__ orow =
        reinterpret_cast<float4*>(out + ((size_t)b * L_DIM + t) * H_DIM);
    __stcs(orow + c,      a0);
    __stcs(orow + c + TB, a1);
}

extern "C" void kernel_launch(void* const* d_in, const int* in_sizes, int n_in,
                              void* d_out, int out_size)
{
    const float* x   = (const float*)d_in[0];   // sequence_output [B,L,H] fp32
    const int*   w2t = (const int*)  d_in[1];   // wordpiece_to_token [B,L] int32
    float*       out = (float*)d_out;           // [B,L,H] fp32

    dim3 gridA(L_DIM / 256, B_DIM);
    seg_bounds_kernel<<<gridA, 256>>>(w2t);

    // phase B: programmatic dependent launch — prologue overlaps phase A
    cudaLaunchConfig_t cfg = {};
    cfg.gridDim  = dim3(L_DIM, B_DIM);
    cfg.blockDim = dim3(TB);
    cfg.dynamicSmemBytes = 0;
    cfg.stream = 0;
    cudaLaunchAttribute attr[1];
    attr[0].id = cudaLaunchAttributeProgrammaticStreamSerialization;
    attr[0].val.programmaticStreamSerializationAllowed = 1;
    cfg.attrs = attr;
    cfg.numAttrs = 1;
    cudaLaunchKernelEx(&cfg, token_segsum_kernel, x, out);
}

// round 10
// speedup vs baseline: 1.0131x; 1.0131x over previous
#include <cuda_runtime.h>

// TokenEmbedding segment-sum, two-phase:
//   Phase A: scatter packed bounds seg2[b][t] = (start[t], start[t+1]).
//   Phase B: one CTA per (b, 2 tokens), 128 threads, 2 float4 cols/thread.
//            The two tokens are processed SEQUENTIALLY reusing the same
//            accumulators: regs/occupancy identical to the 1-token champion,
//            but half the blocks -> per-block fixed costs (dispatch, bounds
//            latency, prologue) amortized 2x. Both tokens' bounds come from
//            ONE 16B int4 load; their row ranges are adjacent so the stream
//            stays sequential and token0's stores overlap token1's loads.
//            Self-covering L2 prefetch of rows {2t, 2t+1} (global bijection).

#define B_DIM 8
#define L_DIM 4096
#define H_DIM 1024
#define H4   (H_DIM / 4)   // 256 float4 per row
#define TB   128           // phase-B threads; each owns 2 float4 columns

// packed bounds: seg2[b][t] = { start[t], start[t+1] }, 16B-aligned pairs
__device__ __align__(16) int2 g_seg2[B_DIM][L_DIM];

__global__ __launch_bounds__(256) void seg_bounds_kernel(
    const int* __restrict__ w2t)      // [B, L] sorted per row
{
    const int b = blockIdx.y;
    const int w = blockIdx.x * blockDim.x + threadIdx.x;
    if (w >= L_DIM) return;

    const int* idx = w2t + (size_t)b * L_DIM;
    const int cur  = __ldg(idx + w);
    const int prev = (w > 0) ? __ldg(idx + w - 1) : -1;

    for (int t = prev + 1; t <= cur; ++t) {
        g_seg2[b][t].x = w;                  // lo of token t
        if (t >= 1) g_seg2[b][t - 1].y = w;  // hi of token t-1
    }
    if (w == L_DIM - 1) {
        for (int t = cur + 1; t <= L_DIM; ++t) {
            if (t < L_DIM) g_seg2[b][t].x = L_DIM;
            g_seg2[b][t - 1].y = L_DIM;
        }
    }
}

__global__ __launch_bounds__(TB) void token_segsum_kernel(
    const float* __restrict__ x,      // [B, L, H]
    float*       __restrict__ out)    // [B, L, H]
{
    const int t0 = blockIdx.x * 2;  // first of two tokens
    const int b  = blockIdx.y;      // batch

    const float* __restrict__ xb = x + (size_t)b * L_DIM * H_DIM;

    // --- prologue: self-covering L2 prefetch of rows t0, t0+1 ---
    // 2 rows x 32 lines of 128B; threads 0..63 prefetch one line each.
    if (threadIdx.x < 64) {
        const float* p = xb + (size_t)t0 * H_DIM + threadIdx.x * 32;
        asm volatile("prefetch.global.L2 [%0];" :: "l"(p));
    }

    // one 16B load = bounds of both tokens (L2-hot broadcast)
    const int4 bnd = __ldg(reinterpret_cast<const int4*>(&g_seg2[b][t0]));
    // token0: [bnd.x, bnd.y), token1: [bnd.z, bnd.w)

    const int c = threadIdx.x;  // float4 column 0..127 (also owns c+128)
    const float4* __restrict__ rows = reinterpret_cast<const float4*>(xb);

    float4* __restrict__ orow =
        reinterpret_cast<float4*>(out + ((size_t)b * L_DIM + t0) * H_DIM);

    // ---- token 0 ----
    {
        float4 a0 = make_float4(0.f, 0.f, 0.f, 0.f);
        float4 a1 = a0;
        for (int w = bnd.x; w < bnd.y; ++w) {
            const float4* r = rows + (size_t)w * H4;
            float4 v0 = __ldcs(r + c);
            float4 v1 = __ldcs(r + c + TB);
            a0.x += v0.x; a0.y += v0.y; a0.z += v0.z; a0.w += v0.w;
            a1.x += v1.x; a1.y += v1.y; a1.z += v1.z; a1.w += v1.w;
        }
        __stcs(orow + c,      a0);
        __stcs(orow + c + TB, a1);
    }

    // ---- token 1 (reuses registers; stores above overlap these loads) ----
    {
        float4 a0 = make_float4(0.f, 0.f, 0.f, 0.f);
        float4 a1 = a0;
        for (int w = bnd.z; w < bnd.w; ++w) {
            const float4* r = rows + (size_t)w * H4;
            float4 v0 = __ldcs(r + c);
            float4 v1 = __ldcs(r + c + TB);
            a0.x += v0.x; a0.y += v0.y; a0.z += v0.z; a0.w += v0.w;
            a1.x += v1.x; a1.y += v1.y; a1.z += v1.z; a1.w += v1.w;
        }
        __stcs(orow + H4 + c,      a0);
        __stcs(orow + H4 + c + TB, a1);
    }
}

extern "C" void kernel_launch(void* const* d_in, const int* in_sizes, int n_in,
                              void* d_out, int out_size)
{
    const float* x   = (const float*)d_in[0];   // sequence_output [B,L,H] fp32
    const int*   w2t = (const int*)  d_in[1];   // wordpiece_to_token [B,L] int32
    float*       out = (float*)d_out;           // [B,L,H] fp32

    dim3 gridA(L_DIM / 256, B_DIM);
    seg_bounds_kernel<<<gridA, 256>>>(w2t);

    dim3 gridB(L_DIM / 2, B_DIM);
    token_segsum_kernel<<<gridB, TB>>>(x, out);
}

// round 11
// speedup vs baseline: 1.0775x; 1.0636x over previous
#include <cuda_runtime.h>

// TokenEmbedding segment-sum, SINGLE kernel:
//   Bounds via warp-parallel windowed counting (no phase A, no scratch table):
//     lo(t) = #{w : idx[w] < t}. idx is sorted uniform -> the boundary lies
//     within +-128 of t with overwhelming probability. Warp 0 loads a 256-int
//     window, counts (<t) and (<t+1) via __reduce_add_sync, validates the
//     window edges, and falls back to binary search on the (rare) miss.
//   Warp 1 concurrently issues the self-covering L2 prefetch of row w==t
//   (t<->w bijection over the grid), overlapping search and row fetch.
//   Then all 128 threads run the champion streaming loop (2 float4 cols each).

#define B_DIM 8
#define L_DIM 4096
#define H_DIM 1024
#define H4   (H_DIM / 4)   // 256 float4 per row
#define TB   128           // threads; each owns 2 float4 columns
#define WIN  256           // search window (ints), +-4 sigma around t

__device__ __forceinline__ int lower_bound_i32(const int* __restrict__ a, int n, int key) {
    int lo = 0, hi = n;
    while (lo < hi) {
        int mid = (lo + hi) >> 1;
        if (__ldg(a + mid) < key) lo = mid + 1;
        else                      hi = mid;
    }
    return lo;
}

__global__ __launch_bounds__(TB) void token_segsum_kernel(
    const float* __restrict__ x,      // [B, L, H]
    const int*   __restrict__ w2t,    // [B, L] sorted per row
    float*       __restrict__ out)    // [B, L, H]
{
    const int t = blockIdx.x;   // token id
    const int b = blockIdx.y;   // batch

    const float* __restrict__ xb  = x  + (size_t)b * L_DIM * H_DIM;
    const int*   __restrict__ idx = w2t + (size_t)b * L_DIM;

    const int warp = threadIdx.x >> 5;
    const int lane = threadIdx.x & 31;

    __shared__ int s_lo, s_hi;

    if (warp == 1) {
        // self-covering L2 prefetch of row t: 32 x 128B lines
        const float* p = xb + (size_t)t * H_DIM + lane * 32;
        asm volatile("prefetch.global.L2 [%0];" :: "l"(p));
    }

    if (warp == 0) {
        // window start: centered at t, clamped, 16B-aligned
        int s = t - WIN / 2;
        if (s < 0) s = 0;
        if (s > L_DIM - WIN) s = L_DIM - WIN;
        s &= ~3;

        const int4* wp = reinterpret_cast<const int4*>(idx + s);
        const int4 va = __ldg(wp + 2 * lane);
        const int4 vb = __ldg(wp + 2 * lane + 1);

        const int t1 = t + 1;
        int cnt  = (va.x < t)  + (va.y < t)  + (va.z < t)  + (va.w < t)
                 + (vb.x < t)  + (vb.y < t)  + (vb.z < t)  + (vb.w < t);
        int cnt1 = (va.x < t1) + (va.y < t1) + (va.z < t1) + (va.w < t1)
                 + (vb.x < t1) + (vb.y < t1) + (vb.z < t1) + (vb.w < t1);

        cnt  = __reduce_add_sync(0xffffffffu, cnt);
        cnt1 = __reduce_add_sync(0xffffffffu, cnt1);

        // coverage check: everything left of the window must be < t,
        // everything right of it must be >= t+1
        const int leftv  = __shfl_sync(0xffffffffu, va.x, 0);   // idx[s]
        const int rightv = __shfl_sync(0xffffffffu, vb.w, 31);  // idx[s+WIN-1]
        const bool ok = (s == 0        || leftv  <  t)
                     && (s + WIN >= L_DIM || rightv >= t1);

        if (lane == 0) {
            int lo, hi;
            if (ok) { lo = s + cnt; hi = s + cnt1; }
            else {  // rare fallback
                lo = lower_bound_i32(idx, L_DIM, t);
                hi = lower_bound_i32(idx, L_DIM, t1);
            }
            s_lo = lo;
            s_hi = hi;
        }
    }
    __syncthreads();

    const int lo = s_lo;
    const int hi = s_hi;

    const int c = threadIdx.x;  // float4 column 0..127 (also owns c+128)
    const float4* __restrict__ rows = reinterpret_cast<const float4*>(xb);

    float4 a0 = make_float4(0.f, 0.f, 0.f, 0.f);
    float4 a1 = a0;

    for (int w = lo; w < hi; ++w) {
        const float4* r = rows + (size_t)w * H4;
        float4 v0 = __ldcs(r + c);
        float4 v1 = __ldcs(r + c + TB);
        a0.x += v0.x; a0.y += v0.y; a0.z += v0.z; a0.w += v0.w;
        a1.x += v1.x; a1.y += v1.y; a1.z += v1.z; a1.w += v1.w;
    }

    float4* __restrict__ orow =
        reinterpret_cast<float4*>(out + ((size_t)b * L_DIM + t) * H_DIM);
    __stcs(orow + c,      a0);
    __stcs(orow + c + TB, a1);
}

extern "C" void kernel_launch(void* const* d_in, const int* in_sizes, int n_in,
                              void* d_out, int out_size)
{
    const float* x   = (const float*)d_in[0];   // sequence_output [B,L,H] fp32
    const int*   w2t = (const int*)  d_in[1];   // wordpiece_to_token [B,L] int32
    float*       out = (float*)d_out;           // [B,L,H] fp32

    dim3 grid(L_DIM, B_DIM);
    token_segsum_kernel<<<grid, TB>>>(x, w2t, out);
}